// round 1
// baseline (speedup 1.0000x reference)
#include <cuda_runtime.h>
#include <math.h>

#define NN 4096
#define F_IN 128
#define F_OUT 64
#define HH 4
#define NEG_INF -1e9f
#define LN_EPS 1e-5f

// ---------------- scratch (device globals: allocation-free) ----------------
__device__ float g_mask[(size_t)NN * NN];             // 64 MB
__device__ float g_proj[HH * NN * F_OUT];             // 4 MB  [h][n][o]
__device__ float g_skip[NN * HH * F_OUT];             // 4 MB  [n][h*64+o]
__device__ float g_ssrc[HH * NN];
__device__ float g_stgt[HH * NN];
__device__ float g_part[32 * HH * NN];                // deterministic partial col-sums
__device__ float g_denom[HH * NN];

// ---------------- k0: per-head projection + skip projection ----------------
// grid 256, block 256. Each block: 16 nodes.
__global__ void k0_proj_skip(const float* __restrict__ nodes,
                             const float* __restrict__ pp,     // [H][F_IN][F_OUT]
                             const float* __restrict__ skw) {  // [256][F_IN]
    __shared__ float xs[16][F_IN];
    const int nbase = blockIdx.x * 16;
    const int tid = threadIdx.x;
    for (int q = tid; q < 16 * F_IN; q += 256)
        xs[q >> 7][q & 127] = nodes[nbase * F_IN + q];
    __syncthreads();

    const int h = tid >> 6, o = tid & 63;
    float acc[16];
#pragma unroll
    for (int k = 0; k < 16; k++) acc[k] = 0.f;
    for (int f = 0; f < F_IN; f++) {
        float w = pp[h * F_IN * F_OUT + f * F_OUT + o];
#pragma unroll
        for (int k = 0; k < 16; k++) acc[k] += xs[k][f] * w;
    }
#pragma unroll
    for (int k = 0; k < 16; k++)
        g_proj[(h * NN + nbase + k) * F_OUT + o] = acc[k];

#pragma unroll
    for (int k = 0; k < 16; k++) acc[k] = 0.f;
    for (int f = 0; f < F_IN; f++) {
        float w = skw[tid * F_IN + f];
#pragma unroll
        for (int k = 0; k < 16; k++) acc[k] += xs[k][f] * w;
    }
#pragma unroll
    for (int k = 0; k < 16; k++)
        g_skip[(nbase + k) * (HH * F_OUT) + tid] = acc[k];
}

// ---------------- k0b: scalar scores s_src/s_tgt (one warp per (h,n)) ------
// grid 2048, block 256 (8 warps) -> 16384 warps = H*N
__global__ void k0b_scores(const float* __restrict__ wsrc,   // [H][64]
                           const float* __restrict__ wtgt) { // [H][64]
    const int warp = (blockIdx.x * blockDim.x + threadIdx.x) >> 5;
    const int lane = threadIdx.x & 31;
    const int h = warp >> 12;
    const int n = warp & (NN - 1);
    const float* pr = &g_proj[(h * NN + n) * F_OUT];
    const float p0 = pr[lane], p1 = pr[lane + 32];
    float a = p0 * wsrc[h * F_OUT + lane] + p1 * wsrc[h * F_OUT + 32 + lane];
    float b = p0 * wtgt[h * F_OUT + lane] + p1 * wtgt[h * F_OUT + 32 + lane];
#pragma unroll
    for (int off = 16; off; off >>= 1) {
        a += __shfl_down_sync(0xffffffffu, a, off);
        b += __shfl_down_sync(0xffffffffu, b, off);
    }
    if (lane == 0) { g_ssrc[h * NN + n] = a; g_stgt[h * NN + n] = b; }
}

// ---------------- k1: mask + row LayerNorm (one block per row) -------------
__global__ void k1_mask_ln(const float* __restrict__ deg,
                           const float* __restrict__ bond,
                           const int* __restrict__ cutoff_p,
                           float* __restrict__ ln_out) {
    const int i = blockIdx.x;
    const int tid = threadIdx.x;
    const float cut = (float)(*cutoff_p);  // value is 0 -> same bits for int/f32
    const size_t row = (size_t)i * NN;

    float mv[16];
    double ds = 0.0, ds2 = 0.0;
#pragma unroll
    for (int k = 0; k < 16; k++) {
        const int j = k * 256 + tid;
        const float d = deg[row + j], b = bond[row + j];
        const float w = d + b;
        const float m = (w > 0.f) ? w : ((b > cut) ? (b + w) : NEG_INF);
        mv[k] = m;
        g_mask[row + j] = m;
        ds += m;
        ds2 += (double)m * (double)m;
    }
    __shared__ double rs[8], rs2[8];
    const int lane = tid & 31, wp = tid >> 5;
#pragma unroll
    for (int off = 16; off; off >>= 1) {
        ds += __shfl_down_sync(0xffffffffu, ds, off);
        ds2 += __shfl_down_sync(0xffffffffu, ds2, off);
    }
    if (lane == 0) { rs[wp] = ds; rs2[wp] = ds2; }
    __syncthreads();
    if (wp == 0) {
        double a = (lane < 8) ? rs[lane] : 0.0;
        double a2 = (lane < 8) ? rs2[lane] : 0.0;
#pragma unroll
        for (int off = 4; off; off >>= 1) {
            a += __shfl_down_sync(0xffffffffu, a, off);
            a2 += __shfl_down_sync(0xffffffffu, a2, off);
        }
        if (lane == 0) { rs[0] = a; rs2[0] = a2; }
    }
    __syncthreads();
    const double mu = rs[0] / NN;
    const double var = rs2[0] / NN - mu * mu;
    const float rstd = (float)(1.0 / sqrt(var + (double)LN_EPS));
    const float muf = (float)mu;
#pragma unroll
    for (int k = 0; k < 16; k++) {
        const int j = k * 256 + tid;
        ln_out[row + j] = (mv[k] - muf) * rstd;
    }
}

// ---------------- k2: column-wise exp partial sums (deterministic) ---------
// grid (16, 32): x = j-tile of 256, y = i-chunk of 128
__global__ void k2_colsum() {
    const int j = blockIdx.x * 256 + threadIdx.x;
    const int ibase = blockIdx.y * 128;
    __shared__ float ss[HH][128];
    for (int q = threadIdx.x; q < HH * 128; q += 256) {
        const int h = q >> 7, ii = q & 127;
        ss[h][ii] = g_ssrc[h * NN + ibase + ii];
    }
    __syncthreads();

    float st[HH], acc[HH];
#pragma unroll
    for (int h = 0; h < HH; h++) { st[h] = g_stgt[h * NN + j]; acc[h] = 0.f; }
    for (int ii = 0; ii < 128; ii++) {
        const float m = g_mask[(size_t)(ibase + ii) * NN + j];
#pragma unroll
        for (int h = 0; h < HH; h++) {
            float a = ss[h][ii] + st[h];
            a = (a > 0.f) ? a : 0.2f * a;
            acc[h] += __expf(a + m);
        }
    }
#pragma unroll
    for (int h = 0; h < HH; h++)
        g_part[(blockIdx.y * HH + h) * NN + j] = acc[h];
}

__global__ void k2b_reduce() {
    const int id = blockIdx.x * 256 + threadIdx.x;  // 0..16383 = h*NN+j
    float s = 0.f;
#pragma unroll 8
    for (int c = 0; c < 32; c++) s += g_part[c * HH * NN + id];
    g_denom[id] = s;
}

// ---------------- k3: attention aggregation + skip + ELU -------------------
// grid (128, 2): x = i-block of 32 rows, y = head group (2 heads)
// block 128 threads: (hh = tid>>6, f = tid&63)
__global__ void __launch_bounds__(128, 3) k3_agg(float* __restrict__ out) {
    const int ibase = blockIdx.x * 32;
    const int hg = blockIdx.y;
    const int tid = threadIdx.x;
    const int hh = tid >> 6;
    const int f = tid & 63;
    const int h = hg * 2 + hh;

    __shared__ float m_s[32][133];                 // padded: conflict-free column reads
    __shared__ __align__(16) float w_s[2][128][36];// padded to 36 (16B-multiple stride)
    __shared__ float st_s[2][128];
    __shared__ float rd_s[2][128];
    __shared__ float ss_s[2][32];

    if (tid < 64) {
        const int h2 = tid >> 5, ii = tid & 31;
        ss_s[h2][ii] = g_ssrc[(hg * 2 + h2) * NN + ibase + ii];
    }

    float acc[32];
#pragma unroll
    for (int k = 0; k < 32; k++) acc[k] = 0.f;

    const int ii_p = tid & 31;  // producer row
    const int jg_p = tid >> 5;  // producer col group 0..3

    for (int jt = 0; jt < 32; jt++) {
        const int jbase = jt * 128;
        __syncthreads();  // previous tile fully consumed
        // stage st/rdenom
        for (int q = tid; q < 256; q += 128) {
            const int h2 = q >> 7, jj = q & 127;
            st_s[h2][jj] = g_stgt[(hg * 2 + h2) * NN + jbase + jj];
            rd_s[h2][jj] = 1.0f / g_denom[(hg * 2 + h2) * NN + jbase + jj];
        }
        // stage mask tile (coalesced)
        for (int q = tid; q < 32 * 128; q += 128) {
            const int r = q >> 7, c = q & 127;
            m_s[r][c] = g_mask[(size_t)(ibase + r) * NN + jbase + c];
        }
        __syncthreads();
        // produce normalized weights
        {
            const float ssv0 = ss_s[0][ii_p];
            const float ssv1 = ss_s[1][ii_p];
#pragma unroll
            for (int jj0 = 0; jj0 < 128; jj0 += 4) {
                const int jj = jj0 + jg_p;
                const float mv = m_s[ii_p][jj];
                float a0 = ssv0 + st_s[0][jj]; a0 = (a0 > 0.f) ? a0 : 0.2f * a0;
                float a1 = ssv1 + st_s[1][jj]; a1 = (a1 > 0.f) ? a1 : 0.2f * a1;
                w_s[0][jj][ii_p] = __expf(a0 + mv) * rd_s[0][jj];
                w_s[1][jj][ii_p] = __expf(a1 + mv) * rd_s[1][jj];
            }
        }
        __syncthreads();
        // consume: acc[ii] += w[h][ii][jj] * proj[h][j][f]
        const float* projh = &g_proj[(h * NN + jbase) * F_OUT + f];
#pragma unroll 2
        for (int jj = 0; jj < 128; jj++) {
            const float pv = __ldg(projh + jj * F_OUT);
            const float* wp = &w_s[hh][jj][0];
            const float4 w0 = *(const float4*)(wp + 0);
            const float4 w1 = *(const float4*)(wp + 4);
            const float4 w2 = *(const float4*)(wp + 8);
            const float4 w3 = *(const float4*)(wp + 12);
            const float4 w4v = *(const float4*)(wp + 16);
            const float4 w5 = *(const float4*)(wp + 20);
            const float4 w6 = *(const float4*)(wp + 24);
            const float4 w7 = *(const float4*)(wp + 28);
            acc[0] += w0.x * pv;  acc[1] += w0.y * pv;  acc[2] += w0.z * pv;  acc[3] += w0.w * pv;
            acc[4] += w1.x * pv;  acc[5] += w1.y * pv;  acc[6] += w1.z * pv;  acc[7] += w1.w * pv;
            acc[8] += w2.x * pv;  acc[9] += w2.y * pv;  acc[10] += w2.z * pv; acc[11] += w2.w * pv;
            acc[12] += w3.x * pv; acc[13] += w3.y * pv; acc[14] += w3.z * pv; acc[15] += w3.w * pv;
            acc[16] += w4v.x * pv; acc[17] += w4v.y * pv; acc[18] += w4v.z * pv; acc[19] += w4v.w * pv;
            acc[20] += w5.x * pv; acc[21] += w5.y * pv; acc[22] += w5.z * pv; acc[23] += w5.w * pv;
            acc[24] += w6.x * pv; acc[25] += w6.y * pv; acc[26] += w6.z * pv; acc[27] += w6.w * pv;
            acc[28] += w7.x * pv; acc[29] += w7.y * pv; acc[30] += w7.z * pv; acc[31] += w7.w * pv;
        }
    }

    // epilogue: + skip, ELU, write
#pragma unroll
    for (int k = 0; k < 32; k++) {
        const int n = ibase + k;
        float v = acc[k] + g_skip[n * (HH * F_OUT) + h * F_OUT + f];
        v = (v > 0.f) ? v : (__expf(v) - 1.f);
        out[n * (HH * F_OUT) + h * F_OUT + f] = v;
    }
}

// ---------------- launch ---------------------------------------------------
extern "C" void kernel_launch(void* const* d_in, const int* in_sizes, int n_in,
                              void* d_out, int out_size) {
    const float* nodes = (const float*)d_in[0];
    const float* deg   = (const float*)d_in[1];
    // d_in[2] = edges_features_distance: unused by the reference
    const float* bond  = (const float*)d_in[3];
    const float* pp    = (const float*)d_in[4];
    const float* wsrc  = (const float*)d_in[5];
    const float* wtgt  = (const float*)d_in[6];
    const float* skw   = (const float*)d_in[7];
    const int*   cut   = (const int*)d_in[8];

    float* out    = (float*)d_out;                       // [N, H*F_OUT]
    float* ln_out = (float*)d_out + (size_t)NN * HH * F_OUT;  // [N, N]

    k0_proj_skip<<<256, 256>>>(nodes, pp, skw);
    k0b_scores<<<2048, 256>>>(wsrc, wtgt);
    k1_mask_ln<<<NN, 256>>>(deg, bond, cut, ln_out);
    k2_colsum<<<dim3(16, 32), 256>>>();
    k2b_reduce<<<64, 256>>>();
    k3_agg<<<dim3(128, 2), 128>>>(out);
}

// round 2
// speedup vs baseline: 1.7829x; 1.7829x over previous
#include <cuda_runtime.h>
#include <math.h>
#include <stdint.h>

#define NN 4096
#define F_IN 128
#define F_OUT 64
#define HH 4
#define NEG_INF -1e9f
#define LN_EPS 1e-5f

// ---------------- scratch (device globals: allocation-free) ----------------
__device__ float g_mask[(size_t)NN * NN];             // 64 MB
__device__ float g_proj[HH * NN * F_OUT];             // 4 MB  [h][n][o]
__device__ float g_projt[HH * NN * F_OUT];            // 4 MB  tf32-rounded
__device__ float g_skip[NN * HH * F_OUT];             // 4 MB  [n][h*64+o]
__device__ float g_ssrc[HH * NN];
__device__ float g_stgt[HH * NN];
__device__ float g_part[32 * HH * NN];                // deterministic partial col-sums
__device__ float g_denom[HH * NN];                    // stores RECIPROCAL of col sums

// ---------------- k0: per-head projection + skip projection ----------------
__global__ void k0_proj_skip(const float* __restrict__ nodes,
                             const float* __restrict__ pp,     // [H][F_IN][F_OUT]
                             const float* __restrict__ skw) {  // [256][F_IN]
    __shared__ float xs[16][F_IN];
    const int nbase = blockIdx.x * 16;
    const int tid = threadIdx.x;
    for (int q = tid; q < 16 * F_IN; q += 256)
        xs[q >> 7][q & 127] = nodes[nbase * F_IN + q];
    __syncthreads();

    const int h = tid >> 6, o = tid & 63;
    float acc[16];
#pragma unroll
    for (int k = 0; k < 16; k++) acc[k] = 0.f;
    for (int f = 0; f < F_IN; f++) {
        float w = pp[h * F_IN * F_OUT + f * F_OUT + o];
#pragma unroll
        for (int k = 0; k < 16; k++) acc[k] += xs[k][f] * w;
    }
#pragma unroll
    for (int k = 0; k < 16; k++)
        g_proj[(h * NN + nbase + k) * F_OUT + o] = acc[k];

#pragma unroll
    for (int k = 0; k < 16; k++) acc[k] = 0.f;
    for (int f = 0; f < F_IN; f++) {
        float w = skw[tid * F_IN + f];
#pragma unroll
        for (int k = 0; k < 16; k++) acc[k] += xs[k][f] * w;
    }
#pragma unroll
    for (int k = 0; k < 16; k++)
        g_skip[(nbase + k) * (HH * F_OUT) + tid] = acc[k];
}

// ---------------- k0b: scalar scores s_src/s_tgt ---------------------------
__global__ void k0b_scores(const float* __restrict__ wsrc,
                           const float* __restrict__ wtgt) {
    const int warp = (blockIdx.x * blockDim.x + threadIdx.x) >> 5;
    const int lane = threadIdx.x & 31;
    const int h = warp >> 12;
    const int n = warp & (NN - 1);
    const float* pr = &g_proj[(h * NN + n) * F_OUT];
    const float p0 = pr[lane], p1 = pr[lane + 32];
    float a = p0 * wsrc[h * F_OUT + lane] + p1 * wsrc[h * F_OUT + 32 + lane];
    float b = p0 * wtgt[h * F_OUT + lane] + p1 * wtgt[h * F_OUT + 32 + lane];
#pragma unroll
    for (int off = 16; off; off >>= 1) {
        a += __shfl_down_sync(0xffffffffu, a, off);
        b += __shfl_down_sync(0xffffffffu, b, off);
    }
    if (lane == 0) { g_ssrc[h * NN + n] = a; g_stgt[h * NN + n] = b; }
}

// ---------------- k0c: pre-round proj to tf32 ------------------------------
__global__ void k0c_cvt(void) {
    const int base = (blockIdx.x * 256 + threadIdx.x) * 4;
#pragma unroll
    for (int q = 0; q < 4; q++) {
        uint32_t u;
        asm("cvt.rna.tf32.f32 %0, %1;" : "=r"(u) : "f"(g_proj[base + q]));
        g_projt[base + q] = __uint_as_float(u);
    }
}

// ---------------- k1: mask + row LayerNorm ---------------------------------
__global__ void k1_mask_ln(const float* __restrict__ deg,
                           const float* __restrict__ bond,
                           const int* __restrict__ cutoff_p,
                           float* __restrict__ ln_out) {
    const int i = blockIdx.x;
    const int tid = threadIdx.x;
    const float cut = (float)(*cutoff_p);
    const size_t row = (size_t)i * NN;

    float mv[16];
    double ds = 0.0, ds2 = 0.0;
#pragma unroll
    for (int k = 0; k < 16; k++) {
        const int j = k * 256 + tid;
        const float d = deg[row + j], b = bond[row + j];
        const float w = d + b;
        const float m = (w > 0.f) ? w : ((b > cut) ? (b + w) : NEG_INF);
        mv[k] = m;
        g_mask[row + j] = m;
        ds += m;
        ds2 += (double)m * (double)m;
    }
    __shared__ double rs[8], rs2[8];
    const int lane = tid & 31, wp = tid >> 5;
#pragma unroll
    for (int off = 16; off; off >>= 1) {
        ds += __shfl_down_sync(0xffffffffu, ds, off);
        ds2 += __shfl_down_sync(0xffffffffu, ds2, off);
    }
    if (lane == 0) { rs[wp] = ds; rs2[wp] = ds2; }
    __syncthreads();
    if (wp == 0) {
        double a = (lane < 8) ? rs[lane] : 0.0;
        double a2 = (lane < 8) ? rs2[lane] : 0.0;
#pragma unroll
        for (int off = 4; off; off >>= 1) {
            a += __shfl_down_sync(0xffffffffu, a, off);
            a2 += __shfl_down_sync(0xffffffffu, a2, off);
        }
        if (lane == 0) { rs[0] = a; rs2[0] = a2; }
    }
    __syncthreads();
    const double mu = rs[0] / NN;
    const double var = rs2[0] / NN - mu * mu;
    const float rstd = (float)(1.0 / sqrt(var + (double)LN_EPS));
    const float muf = (float)mu;
#pragma unroll
    for (int k = 0; k < 16; k++) {
        const int j = k * 256 + tid;
        ln_out[row + j] = (mv[k] - muf) * rstd;
    }
}

// ---------------- k2: column-wise exp partial sums (deterministic) ---------
__global__ void k2_colsum() {
    const int j = blockIdx.x * 256 + threadIdx.x;
    const int ibase = blockIdx.y * 128;
    __shared__ float ss[HH][128];
    for (int q = threadIdx.x; q < HH * 128; q += 256) {
        const int h = q >> 7, ii = q & 127;
        ss[h][ii] = g_ssrc[h * NN + ibase + ii];
    }
    __syncthreads();

    float st[HH], acc[HH];
#pragma unroll
    for (int h = 0; h < HH; h++) { st[h] = g_stgt[h * NN + j]; acc[h] = 0.f; }
    for (int ii = 0; ii < 128; ii++) {
        const float m = g_mask[(size_t)(ibase + ii) * NN + j];
#pragma unroll
        for (int h = 0; h < HH; h++) {
            float a = ss[h][ii] + st[h];
            a = (a > 0.f) ? a : 0.2f * a;
            acc[h] += __expf(a + m);
        }
    }
#pragma unroll
    for (int h = 0; h < HH; h++)
        g_part[(blockIdx.y * HH + h) * NN + j] = acc[h];
}

__global__ void k2b_reduce() {
    const int id = blockIdx.x * 256 + threadIdx.x;
    float s = 0.f;
#pragma unroll 8
    for (int c = 0; c < 32; c++) s += g_part[c * HH * NN + id];
    g_denom[id] = 1.0f / s;   // reciprocal, consumed directly by k3
}

// ---------------- k3: tensor-core aggregation (tf32 mma.sync) --------------
// grid 128 (i-tiles of 32 rows), block 256 = 8 warps = 4 heads x 2 m-halves.
// Loop over 64 j-tiles of 64:  D[32,64] += W[32,64] * P[64,64]  per head.
struct K3Smem {
    float w[HH][32][68];   // weights, tf32-rounded; stride 68 -> conflict-free A frags
    float p[HH][64][72];   // proj tile, tf32-rounded; stride 72 -> conflict-free B frags
    float st[HH][64];
    float rd[HH][64];
    float ss[HH][32];
};

__device__ __forceinline__ void mma_tf32(float* c, uint32_t a0, uint32_t a1,
                                         uint32_t a2, uint32_t a3,
                                         uint32_t b0, uint32_t b1) {
    asm volatile(
        "mma.sync.aligned.m16n8k8.row.col.f32.tf32.tf32.f32 "
        "{%0,%1,%2,%3}, {%4,%5,%6,%7}, {%8,%9}, {%0,%1,%2,%3};"
        : "+f"(c[0]), "+f"(c[1]), "+f"(c[2]), "+f"(c[3])
        : "r"(a0), "r"(a1), "r"(a2), "r"(a3), "r"(b0), "r"(b1));
}

__global__ void __launch_bounds__(256, 1) k3_mma(float* __restrict__ out) {
    extern __shared__ char smem_raw[];
    K3Smem* S = (K3Smem*)smem_raw;

    const int tid = threadIdx.x;
    const int ibase = blockIdx.x * 32;
    const int wp = tid >> 5;           // 0..7
    const int lane = tid & 31;
    const int h = wp >> 1;             // head of this warp
    const int mh = (wp & 1) * 16;      // m-half: rows [mh, mh+16)
    const int g = lane >> 2;           // groupID
    const int t = lane & 3;            // threadID in group

    // stage s_src for this i-tile (constant across j-tiles)
    if (tid < HH * 32) {
        const int h2 = tid >> 5, ii = tid & 31;
        S->ss[h2][ii] = g_ssrc[h2 * NN + ibase + ii];
    }

    float acc[8][4];
#pragma unroll
    for (int nt = 0; nt < 8; nt++)
#pragma unroll
        for (int q = 0; q < 4; q++) acc[nt][q] = 0.f;

    for (int jt = 0; jt < 64; jt++) {
        const int jbase = jt * 64;
        __syncthreads();   // previous tile fully consumed

        // stage st / reciprocal denom for this j-tile
        if (tid < HH * 64) {
            const int h2 = tid >> 6, jj = tid & 63;
            S->st[h2][jj] = g_stgt[h2 * NN + jbase + jj];
            S->rd[h2][jj] = g_denom[h2 * NN + jbase + jj];
        }
        __syncthreads();

        // produce normalized weights (tf32-rounded) : 4 heads x 32 x 64
        for (int idx = tid; idx < HH * 32 * 64; idx += 256) {
            const int h2 = idx >> 11;
            const int r = idx & 2047;
            const int ii = r >> 6;
            const int jj = r & 63;
            const float m = g_mask[(size_t)(ibase + ii) * NN + jbase + jj];
            float a = S->ss[h2][ii] + S->st[h2][jj];
            a = fmaxf(a, 0.2f * a);                 // leaky relu
            const float e = __expf(a + m) * S->rd[h2][jj];
            uint32_t u;
            asm("cvt.rna.tf32.f32 %0, %1;" : "=r"(u) : "f"(e));
            S->w[h2][ii][jj] = __uint_as_float(u);
        }

        // stage proj tile (pre-rounded): 4 heads x 64 j x 64 f, float4 copies
        for (int idx4 = tid; idx4 < HH * 64 * 16; idx4 += 256) {
            const int h2 = idx4 >> 10;
            const int r = idx4 & 1023;
            const int k = r >> 4;
            const int n4 = (r & 15) * 4;
            const float4 v = *(const float4*)&g_projt[((h2 * NN) + jbase + k) * F_OUT + n4];
            *(float4*)&S->p[h2][k][n4] = v;
        }
        __syncthreads();

        // tensor contraction: 8 k-steps x 8 n-tiles of m16n8k8
#pragma unroll
        for (int k = 0; k < 8; k++) {
            const int col = k * 8 + t;
            const uint32_t a0 = __float_as_uint(S->w[h][mh + g][col]);
            const uint32_t a1 = __float_as_uint(S->w[h][mh + g + 8][col]);
            const uint32_t a2 = __float_as_uint(S->w[h][mh + g][col + 4]);
            const uint32_t a3 = __float_as_uint(S->w[h][mh + g + 8][col + 4]);
#pragma unroll
            for (int nt = 0; nt < 8; nt++) {
                const uint32_t b0 = __float_as_uint(S->p[h][k * 8 + t][nt * 8 + g]);
                const uint32_t b1 = __float_as_uint(S->p[h][k * 8 + 4 + t][nt * 8 + g]);
                mma_tf32(acc[nt], a0, a1, a2, a3, b0, b1);
            }
        }
    }

    // epilogue: + skip, ELU, write.  c frag: rows (mh+g, mh+g+8), cols (2t, 2t+1)
#pragma unroll
    for (int nt = 0; nt < 8; nt++) {
        const int f0 = nt * 8 + t * 2;
        const int n0 = ibase + mh + g;
        const int n1 = n0 + 8;
#pragma unroll
        for (int q = 0; q < 4; q++) {
            const int n = (q >= 2) ? n1 : n0;
            const int f = f0 + (q & 1);
            const int o = n * (HH * F_OUT) + h * F_OUT + f;
            float v = acc[nt][q] + g_skip[o];
            v = (v > 0.f) ? v : (__expf(v) - 1.f);
            out[o] = v;
        }
    }
}

// ---------------- launch ---------------------------------------------------
extern "C" void kernel_launch(void* const* d_in, const int* in_sizes, int n_in,
                              void* d_out, int out_size) {
    const float* nodes = (const float*)d_in[0];
    const float* deg   = (const float*)d_in[1];
    const float* bond  = (const float*)d_in[3];
    const float* pp    = (const float*)d_in[4];
    const float* wsrc  = (const float*)d_in[5];
    const float* wtgt  = (const float*)d_in[6];
    const float* skw   = (const float*)d_in[7];
    const int*   cut   = (const int*)d_in[8];

    float* out    = (float*)d_out;
    float* ln_out = (float*)d_out + (size_t)NN * HH * F_OUT;

    const int k3_smem = (int)sizeof(K3Smem);
    cudaFuncSetAttribute(k3_mma, cudaFuncAttributeMaxDynamicSharedMemorySize, k3_smem);

    k0_proj_skip<<<256, 256>>>(nodes, pp, skw);
    k0b_scores<<<2048, 256>>>(wsrc, wtgt);
    k0c_cvt<<<1024, 256>>>();
    k1_mask_ln<<<NN, 256>>>(deg, bond, cut, ln_out);
    k2_colsum<<<dim3(16, 32), 256>>>();
    k2b_reduce<<<64, 256>>>();
    k3_mma<<<128, 256, k3_smem>>>(out);
}

// round 3
// speedup vs baseline: 3.3193x; 1.8617x over previous
#include <cuda_runtime.h>
#include <math.h>
#include <stdint.h>

#define NN 4096
#define F_IN 128
#define F_OUT 64
#define HH 4
#define NEG_INF -1e9f
#define LN_EPS 1e-5f

// ---------------- scratch (device globals: allocation-free) ----------------
__device__ float g_mask[(size_t)NN * NN];             // 64 MB
__device__ float g_projt[HH * NN * F_OUT];            // 4 MB  tf32-rounded [h][n][o]
__device__ float g_skip[NN * HH * F_OUT];             // 4 MB  [n][h*64+o]
__device__ float g_ssrc[HH * NN];
__device__ float g_stgt[HH * NN];
__device__ float g_part[32 * HH * NN];                // deterministic partial col-sums
__device__ float g_denom[HH * NN];                    // RECIPROCAL col sums

// ---------------- cp.async helpers -----------------------------------------
__device__ __forceinline__ void cpasync16(void* s, const void* g) {
    uint32_t sa = (uint32_t)__cvta_generic_to_shared(s);
    asm volatile("cp.async.cg.shared.global [%0], [%1], 16;" :: "r"(sa), "l"(g));
}
#define CP_COMMIT() asm volatile("cp.async.commit_group;")
#define CP_WAIT0()  asm volatile("cp.async.wait_group 0;")

// ---------------- k0: fused proj(tf32) + scores + skip ---------------------
// grid 256, block 256. Each block: 16 nodes.
__global__ void k0_fused(const float* __restrict__ nodes,
                         const float* __restrict__ pp,     // [H][F_IN][F_OUT]
                         const float* __restrict__ skw,    // [256][F_IN]
                         const float* __restrict__ wsrc,   // [H][64]
                         const float* __restrict__ wtgt) { // [H][64]
    __shared__ float xs[16][F_IN];
    __shared__ float red[2][2][HH][16];   // [sel src/tgt][warp-half][h][node]
    const int nbase = blockIdx.x * 16;
    const int tid = threadIdx.x;
    for (int q = tid; q < 16 * F_IN; q += 256)
        xs[q >> 7][q & 127] = nodes[nbase * F_IN + q];
    __syncthreads();

    const int h = tid >> 6, o = tid & 63;
    const int lane = tid & 31, half = (tid >> 5) & 1;

    float acc[16];
#pragma unroll
    for (int k = 0; k < 16; k++) acc[k] = 0.f;
    for (int f = 0; f < F_IN; f++) {
        float w = pp[h * F_IN * F_OUT + f * F_OUT + o];
#pragma unroll
        for (int k = 0; k < 16; k++) acc[k] += xs[k][f] * w;
    }
    // tf32-rounded projection for the MMA kernel
#pragma unroll
    for (int k = 0; k < 16; k++) {
        uint32_t u;
        asm("cvt.rna.tf32.f32 %0, %1;" : "=r"(u) : "f"(acc[k]));
        g_projt[(h * NN + nbase + k) * F_OUT + o] = __uint_as_float(u);
    }
    // scores: reduce acc*w over o (64 threads = 2 warps)
    {
        const float ws = wsrc[h * F_OUT + o];
        const float wt = wtgt[h * F_OUT + o];
#pragma unroll
        for (int k = 0; k < 16; k++) {
            float s = acc[k] * ws, t = acc[k] * wt;
#pragma unroll
            for (int off = 16; off; off >>= 1) {
                s += __shfl_down_sync(0xffffffffu, s, off);
                t += __shfl_down_sync(0xffffffffu, t, off);
            }
            if (lane == 0) { red[0][half][h][k] = s; red[1][half][h][k] = t; }
        }
    }
    __syncthreads();
    if (tid < 128) {
        const int h2 = tid >> 5, k = (tid >> 1) & 15, sel = tid & 1;
        const float v = red[sel][0][h2][k] + red[sel][1][h2][k];
        if (sel == 0) g_ssrc[h2 * NN + nbase + k] = v;
        else          g_stgt[h2 * NN + nbase + k] = v;
    }

    // skip projection
#pragma unroll
    for (int k = 0; k < 16; k++) acc[k] = 0.f;
    for (int f = 0; f < F_IN; f++) {
        float w = skw[tid * F_IN + f];
#pragma unroll
        for (int k = 0; k < 16; k++) acc[k] += xs[k][f] * w;
    }
#pragma unroll
    for (int k = 0; k < 16; k++)
        g_skip[(nbase + k) * (HH * F_OUT) + tid] = acc[k];
}

// ---------------- k1: mask + row LayerNorm (float-only, vectorized) --------
__global__ void k1_mask_ln(const float* __restrict__ deg,
                           const float* __restrict__ bond,
                           const int* __restrict__ cutoff_p,
                           float* __restrict__ ln_out) {
    const int i = blockIdx.x;
    const int tid = threadIdx.x;
    const float cut = (float)(*cutoff_p);
    const size_t row = (size_t)i * NN;

    float mv[16];
    float s = 0.f, s2 = 0.f;
#pragma unroll
    for (int k = 0; k < 4; k++) {
        const int j4 = (k * 256 + tid) * 4;
        const float4 d4 = *(const float4*)&deg[row + j4];
        const float4 b4 = *(const float4*)&bond[row + j4];
        float4 m4;
        {
            const float w = d4.x + b4.x;
            m4.x = (w > 0.f) ? w : ((b4.x > cut) ? (b4.x + w) : NEG_INF);
            const float w1 = d4.y + b4.y;
            m4.y = (w1 > 0.f) ? w1 : ((b4.y > cut) ? (b4.y + w1) : NEG_INF);
            const float w2 = d4.z + b4.z;
            m4.z = (w2 > 0.f) ? w2 : ((b4.z > cut) ? (b4.z + w2) : NEG_INF);
            const float w3 = d4.w + b4.w;
            m4.w = (w3 > 0.f) ? w3 : ((b4.w > cut) ? (b4.w + w3) : NEG_INF);
        }
        mv[k * 4 + 0] = m4.x; mv[k * 4 + 1] = m4.y;
        mv[k * 4 + 2] = m4.z; mv[k * 4 + 3] = m4.w;
        *(float4*)&g_mask[row + j4] = m4;
        s  += (m4.x + m4.y) + (m4.z + m4.w);
        s2 += (m4.x * m4.x + m4.y * m4.y) + (m4.z * m4.z + m4.w * m4.w);
    }
    __shared__ float rs[8], rs2[8];
    const int lane = tid & 31, wp = tid >> 5;
#pragma unroll
    for (int off = 16; off; off >>= 1) {
        s  += __shfl_down_sync(0xffffffffu, s, off);
        s2 += __shfl_down_sync(0xffffffffu, s2, off);
    }
    if (lane == 0) { rs[wp] = s; rs2[wp] = s2; }
    __syncthreads();
    if (wp == 0) {
        float a  = (lane < 8) ? rs[lane] : 0.f;
        float a2 = (lane < 8) ? rs2[lane] : 0.f;
#pragma unroll
        for (int off = 4; off; off >>= 1) {
            a  += __shfl_down_sync(0xffffffffu, a, off);
            a2 += __shfl_down_sync(0xffffffffu, a2, off);
        }
        if (lane == 0) { rs[0] = a; rs2[0] = a2; }
    }
    __syncthreads();
    const float mu  = rs[0] * (1.0f / NN);
    const float var = fmaxf(rs2[0] * (1.0f / NN) - mu * mu, 0.f);
    const float rstd = 1.0f / sqrtf(var + LN_EPS);
#pragma unroll
    for (int k = 0; k < 4; k++) {
        const int j4 = (k * 256 + tid) * 4;
        float4 o4;
        o4.x = (mv[k * 4 + 0] - mu) * rstd;
        o4.y = (mv[k * 4 + 1] - mu) * rstd;
        o4.z = (mv[k * 4 + 2] - mu) * rstd;
        o4.w = (mv[k * 4 + 3] - mu) * rstd;
        *(float4*)&ln_out[row + j4] = o4;
    }
}

// ---------------- k2: column-wise exp partial sums (deterministic) ---------
__global__ void k2_colsum() {
    const int j = blockIdx.x * 256 + threadIdx.x;
    const int ibase = blockIdx.y * 128;
    __shared__ float ss[HH][128];
    for (int q = threadIdx.x; q < HH * 128; q += 256) {
        const int h = q >> 7, ii = q & 127;
        ss[h][ii] = g_ssrc[h * NN + ibase + ii];
    }
    __syncthreads();

    float st[HH], acc[HH];
#pragma unroll
    for (int h = 0; h < HH; h++) { st[h] = g_stgt[h * NN + j]; acc[h] = 0.f; }
    for (int ii = 0; ii < 128; ii++) {
        const float m = g_mask[(size_t)(ibase + ii) * NN + j];
#pragma unroll
        for (int h = 0; h < HH; h++) {
            float a = ss[h][ii] + st[h];
            a = fmaxf(a, 0.2f * a);
            acc[h] += __expf(a + m);
        }
    }
#pragma unroll
    for (int h = 0; h < HH; h++)
        g_part[(blockIdx.y * HH + h) * NN + j] = acc[h];
}

__global__ void k2b_reduce() {
    const int id = blockIdx.x * 256 + threadIdx.x;
    float s = 0.f;
#pragma unroll 8
    for (int c = 0; c < 32; c++) s += g_part[c * HH * NN + id];
    g_denom[id] = 1.0f / s;
}

// ---------------- k3: tf32 mma with cp.async double-buffered staging -------
// grid 128 (i-tiles of 32 rows), block 256 = 8 warps = 4 heads x 2 m-halves.
struct K3Smem {
    float m[2][32][64];      // mask tile, double-buffered (16 KB)
    float p[2][HH][64][72];  // proj tile, db; stride 72 -> conflict-free B frags (147 KB)
    float w[HH][32][68];     // weights; stride 68 -> conflict-free A frags (34.8 KB)
    float st[2][HH][64];
    float rd[2][HH][64];
    float ss[HH][32];
};

__device__ __forceinline__ void mma_tf32(float* c, uint32_t a0, uint32_t a1,
                                         uint32_t a2, uint32_t a3,
                                         uint32_t b0, uint32_t b1) {
    asm volatile(
        "mma.sync.aligned.m16n8k8.row.col.f32.tf32.tf32.f32 "
        "{%0,%1,%2,%3}, {%4,%5,%6,%7}, {%8,%9}, {%0,%1,%2,%3};"
        : "+f"(c[0]), "+f"(c[1]), "+f"(c[2]), "+f"(c[3])
        : "r"(a0), "r"(a1), "r"(a2), "r"(a3), "r"(b0), "r"(b1));
}

__device__ __forceinline__ void k3_issue_tile(K3Smem* S, int ibase, int jt,
                                              int buf, int tid) {
    const int jbase = jt * 64;
    // mask tile: 32x64 floats = 512 16B-chunks
#pragma unroll
    for (int c0 = 0; c0 < 512; c0 += 256) {
        const int c = c0 + tid;
        const int r = c >> 4, f4 = (c & 15) << 2;
        cpasync16(&S->m[buf][r][f4], &g_mask[(size_t)(ibase + r) * NN + jbase + f4]);
    }
    // proj tile: 4x64x64 floats = 4096 chunks
#pragma unroll
    for (int c0 = 0; c0 < 4096; c0 += 256) {
        const int c = c0 + tid;
        const int h2 = c >> 10, r = (c >> 4) & 63, f4 = (c & 15) << 2;
        cpasync16(&S->p[buf][h2][r][f4],
                  &g_projt[((h2 * NN) + jbase + r) * F_OUT + f4]);
    }
    // st / rd: 64 chunks each
    if (tid < 64) {
        const int h2 = tid >> 4, j4 = (tid & 15) << 2;
        cpasync16(&S->st[buf][h2][j4], &g_stgt[h2 * NN + jbase + j4]);
    } else if (tid < 128) {
        const int q = tid - 64;
        const int h2 = q >> 4, j4 = (q & 15) << 2;
        cpasync16(&S->rd[buf][h2][j4], &g_denom[h2 * NN + jbase + j4]);
    }
    CP_COMMIT();
}

__global__ void __launch_bounds__(256, 1) k3_mma(float* __restrict__ out) {
    extern __shared__ char smem_raw[];
    K3Smem* S = (K3Smem*)smem_raw;

    const int tid = threadIdx.x;
    const int ibase = blockIdx.x * 32;
    const int wp = tid >> 5;
    const int lane = tid & 31;
    const int h = wp >> 1;
    const int mh = (wp & 1) * 16;
    const int g = lane >> 2;
    const int t = lane & 3;
    const int jj = tid & 63;       // producer column
    const int iofs = tid >> 6;     // producer row offset

    if (tid < HH * 32) {
        const int h2 = tid >> 5, ii = tid & 31;
        S->ss[h2][ii] = g_ssrc[h2 * NN + ibase + ii];
    }

    float acc[8][4];
#pragma unroll
    for (int nt = 0; nt < 8; nt++)
#pragma unroll
        for (int q = 0; q < 4; q++) acc[nt][q] = 0.f;

    k3_issue_tile(S, ibase, 0, 0, tid);

    for (int jt = 0; jt < 64; jt++) {
        const int buf = jt & 1;
        CP_WAIT0();
        __syncthreads();           // data for jt visible; prev MMA done with buf^1
        if (jt + 1 < 64) k3_issue_tile(S, ibase, jt + 1, buf ^ 1, tid);

        // ---- produce normalized weights (all from smem) ----
        float stv[HH], rdv[HH];
#pragma unroll
        for (int h2 = 0; h2 < HH; h2++) {
            stv[h2] = S->st[buf][h2][jj];
            rdv[h2] = S->rd[buf][h2][jj];
        }
#pragma unroll
        for (int p = 0; p < 8; p++) {
            const int ii = p * 4 + iofs;
            const float mvv = S->m[buf][ii][jj];
#pragma unroll
            for (int h2 = 0; h2 < HH; h2++) {
                float a = S->ss[h2][ii] + stv[h2];
                a = fmaxf(a, 0.2f * a);
                const float e = __expf(a + mvv) * rdv[h2];
                uint32_t u;
                asm("cvt.rna.tf32.f32 %0, %1;" : "=r"(u) : "f"(e));
                S->w[h2][ii][jj] = __uint_as_float(u);
            }
        }
        __syncthreads();

        // ---- tensor contraction: 8 k-steps x 8 n-tiles of m16n8k8 ----
#pragma unroll
        for (int k = 0; k < 8; k++) {
            const int col = k * 8 + t;
            const uint32_t a0 = __float_as_uint(S->w[h][mh + g][col]);
            const uint32_t a1 = __float_as_uint(S->w[h][mh + g + 8][col]);
            const uint32_t a2 = __float_as_uint(S->w[h][mh + g][col + 4]);
            const uint32_t a3 = __float_as_uint(S->w[h][mh + g + 8][col + 4]);
#pragma unroll
            for (int nt = 0; nt < 8; nt++) {
                const uint32_t b0 = __float_as_uint(S->p[buf][h][k * 8 + t][nt * 8 + g]);
                const uint32_t b1 = __float_as_uint(S->p[buf][h][k * 8 + 4 + t][nt * 8 + g]);
                mma_tf32(acc[nt], a0, a1, a2, a3, b0, b1);
            }
        }
    }

    // epilogue: + skip, ELU, write
#pragma unroll
    for (int nt = 0; nt < 8; nt++) {
        const int f0 = nt * 8 + t * 2;
        const int n0 = ibase + mh + g;
        const int n1 = n0 + 8;
#pragma unroll
        for (int q = 0; q < 4; q++) {
            const int n = (q >= 2) ? n1 : n0;
            const int f = f0 + (q & 1);
            const int o = n * (HH * F_OUT) + h * F_OUT + f;
            float v = acc[nt][q] + g_skip[o];
            v = (v > 0.f) ? v : (__expf(v) - 1.f);
            out[o] = v;
        }
    }
}

// ---------------- launch ---------------------------------------------------
extern "C" void kernel_launch(void* const* d_in, const int* in_sizes, int n_in,
                              void* d_out, int out_size) {
    const float* nodes = (const float*)d_in[0];
    const float* deg   = (const float*)d_in[1];
    const float* bond  = (const float*)d_in[3];
    const float* pp    = (const float*)d_in[4];
    const float* wsrc  = (const float*)d_in[5];
    const float* wtgt  = (const float*)d_in[6];
    const float* skw   = (const float*)d_in[7];
    const int*   cut   = (const int*)d_in[8];

    float* out    = (float*)d_out;
    float* ln_out = (float*)d_out + (size_t)NN * HH * F_OUT;

    const int k3_smem = (int)sizeof(K3Smem);
    cudaFuncSetAttribute(k3_mma, cudaFuncAttributeMaxDynamicSharedMemorySize, k3_smem);

    k0_fused<<<256, 256>>>(nodes, pp, skw, wsrc, wtgt);
    k1_mask_ln<<<NN, 256>>>(deg, bond, cut, ln_out);
    k2_colsum<<<dim3(16, 32), 256>>>();
    k2b_reduce<<<64, 256>>>();
    k3_mma<<<128, 256, k3_smem>>>(out);
}

// round 4
// speedup vs baseline: 4.5194x; 1.3615x over previous
#include <cuda_runtime.h>
#include <cuda_bf16.h>
#include <math.h>
#include <stdint.h>

#define NN 4096
#define F_IN 128
#define F_OUT 64
#define HH 4
#define NEG_INF -1e9f
#define LN_EPS 1e-5f

// ---------------- scratch (device globals: allocation-free) ----------------
__device__ float g_mask[(size_t)NN * NN];               // 64 MB
__device__ __nv_bfloat16 g_projb[HH * NN * F_OUT];      // 2 MB  bf16 [h][n][o]
__device__ float g_skip[NN * HH * F_OUT];               // 4 MB  [n][h*64+o]
__device__ float g_ssrc[HH * NN];
__device__ float g_stgt[HH * NN];
__device__ float g_part[32 * HH * NN];                  // deterministic partial col-sums
__device__ float g_denom[HH * NN];                      // RECIPROCAL col sums

// ---------------- asm helpers ----------------------------------------------
__device__ __forceinline__ void cpasync16(void* s, const void* g) {
    uint32_t sa = (uint32_t)__cvta_generic_to_shared(s);
    asm volatile("cp.async.cg.shared.global [%0], [%1], 16;" :: "r"(sa), "l"(g));
}
#define CP_COMMIT() asm volatile("cp.async.commit_group;")
#define CP_WAIT0()  asm volatile("cp.async.wait_group 0;")

#define LDSM_X4(r0, r1, r2, r3, a) \
    asm volatile("ldmatrix.sync.aligned.m8n8.x4.shared.b16 {%0,%1,%2,%3}, [%4];" \
                 : "=r"(r0), "=r"(r1), "=r"(r2), "=r"(r3) : "r"(a))
#define LDSM_X4T(r0, r1, r2, r3, a) \
    asm volatile("ldmatrix.sync.aligned.m8n8.x4.trans.shared.b16 {%0,%1,%2,%3}, [%4];" \
                 : "=r"(r0), "=r"(r1), "=r"(r2), "=r"(r3) : "r"(a))

__device__ __forceinline__ void mma_bf16(float* c, uint32_t a0, uint32_t a1,
                                         uint32_t a2, uint32_t a3,
                                         uint32_t b0, uint32_t b1) {
    asm volatile(
        "mma.sync.aligned.m16n8k16.row.col.f32.bf16.bf16.f32 "
        "{%0,%1,%2,%3}, {%4,%5,%6,%7}, {%8,%9}, {%0,%1,%2,%3};"
        : "+f"(c[0]), "+f"(c[1]), "+f"(c[2]), "+f"(c[3])
        : "r"(a0), "r"(a1), "r"(a2), "r"(a3), "r"(b0), "r"(b1));
}

// ---------------- k0: fused proj(bf16) + scores + skip ---------------------
__global__ void k0_fused(const float* __restrict__ nodes,
                         const float* __restrict__ pp,
                         const float* __restrict__ skw,
                         const float* __restrict__ wsrc,
                         const float* __restrict__ wtgt) {
    __shared__ float xs[16][F_IN];
    __shared__ float red[2][2][HH][16];
    const int nbase = blockIdx.x * 16;
    const int tid = threadIdx.x;
    for (int q = tid; q < 16 * F_IN; q += 256)
        xs[q >> 7][q & 127] = nodes[nbase * F_IN + q];
    __syncthreads();

    const int h = tid >> 6, o = tid & 63;
    const int lane = tid & 31, half = (tid >> 5) & 1;

    float acc[16];
#pragma unroll
    for (int k = 0; k < 16; k++) acc[k] = 0.f;
    for (int f = 0; f < F_IN; f++) {
        float w = pp[h * F_IN * F_OUT + f * F_OUT + o];
#pragma unroll
        for (int k = 0; k < 16; k++) acc[k] += xs[k][f] * w;
    }
#pragma unroll
    for (int k = 0; k < 16; k++)
        g_projb[(h * NN + nbase + k) * F_OUT + o] = __float2bfloat16_rn(acc[k]);

    {
        const float ws = wsrc[h * F_OUT + o];
        const float wt = wtgt[h * F_OUT + o];
#pragma unroll
        for (int k = 0; k < 16; k++) {
            float s = acc[k] * ws, t = acc[k] * wt;
#pragma unroll
            for (int off = 16; off; off >>= 1) {
                s += __shfl_down_sync(0xffffffffu, s, off);
                t += __shfl_down_sync(0xffffffffu, t, off);
            }
            if (lane == 0) { red[0][half][h][k] = s; red[1][half][h][k] = t; }
        }
    }
    __syncthreads();
    if (tid < 128) {
        const int h2 = tid >> 5, k = (tid >> 1) & 15, sel = tid & 1;
        const float v = red[sel][0][h2][k] + red[sel][1][h2][k];
        if (sel == 0) g_ssrc[h2 * NN + nbase + k] = v;
        else          g_stgt[h2 * NN + nbase + k] = v;
    }

#pragma unroll
    for (int k = 0; k < 16; k++) acc[k] = 0.f;
    for (int f = 0; f < F_IN; f++) {
        float w = skw[tid * F_IN + f];
#pragma unroll
        for (int k = 0; k < 16; k++) acc[k] += xs[k][f] * w;
    }
#pragma unroll
    for (int k = 0; k < 16; k++)
        g_skip[(nbase + k) * (HH * F_OUT) + tid] = acc[k];
}

// ---------------- k1: mask + row LayerNorm (512 thr, streaming) ------------
__global__ void k1_mask_ln(const float* __restrict__ deg,
                           const float* __restrict__ bond,
                           const int* __restrict__ cutoff_p,
                           float* __restrict__ ln_out) {
    const int i = blockIdx.x;
    const int tid = threadIdx.x;
    const float cut = (float)(*cutoff_p);
    const size_t row = (size_t)i * NN;

    float4 m4[2];
    float s = 0.f, s2 = 0.f;
#pragma unroll
    for (int k = 0; k < 2; k++) {
        const int j4 = (k * 512 + tid) * 4;
        const float4 d4 = __ldcs((const float4*)&deg[row + j4]);
        const float4 b4 = __ldcs((const float4*)&bond[row + j4]);
        float4 m;
        float w;
        w = d4.x + b4.x; m.x = (w > 0.f) ? w : ((b4.x > cut) ? (b4.x + w) : NEG_INF);
        w = d4.y + b4.y; m.y = (w > 0.f) ? w : ((b4.y > cut) ? (b4.y + w) : NEG_INF);
        w = d4.z + b4.z; m.z = (w > 0.f) ? w : ((b4.z > cut) ? (b4.z + w) : NEG_INF);
        w = d4.w + b4.w; m.w = (w > 0.f) ? w : ((b4.w > cut) ? (b4.w + w) : NEG_INF);
        m4[k] = m;
        *(float4*)&g_mask[row + j4] = m;
        s  += (m.x + m.y) + (m.z + m.w);
        s2 += (m.x * m.x + m.y * m.y) + (m.z * m.z + m.w * m.w);
    }
    __shared__ float rs[16], rs2[16];
    const int lane = tid & 31, wp = tid >> 5;
#pragma unroll
    for (int off = 16; off; off >>= 1) {
        s  += __shfl_down_sync(0xffffffffu, s, off);
        s2 += __shfl_down_sync(0xffffffffu, s2, off);
    }
    if (lane == 0) { rs[wp] = s; rs2[wp] = s2; }
    __syncthreads();
    if (wp == 0) {
        float a  = (lane < 16) ? rs[lane] : 0.f;
        float a2 = (lane < 16) ? rs2[lane] : 0.f;
#pragma unroll
        for (int off = 8; off; off >>= 1) {
            a  += __shfl_down_sync(0xffffffffu, a, off);
            a2 += __shfl_down_sync(0xffffffffu, a2, off);
        }
        if (lane == 0) { rs[0] = a; rs2[0] = a2; }
    }
    __syncthreads();
    const float mu  = rs[0] * (1.0f / NN);
    const float var = fmaxf(rs2[0] * (1.0f / NN) - mu * mu, 0.f);
    const float rstd = 1.0f / sqrtf(var + LN_EPS);
#pragma unroll
    for (int k = 0; k < 2; k++) {
        const int j4 = (k * 512 + tid) * 4;
        float4 o4;
        o4.x = (m4[k].x - mu) * rstd;
        o4.y = (m4[k].y - mu) * rstd;
        o4.z = (m4[k].z - mu) * rstd;
        o4.w = (m4[k].w - mu) * rstd;
        __stcs((float4*)&ln_out[row + j4], o4);
    }
}

// ---------------- k2: column-wise exp partial sums (deterministic) ---------
__global__ void k2_colsum() {
    const int j = blockIdx.x * 256 + threadIdx.x;
    const int ibase = blockIdx.y * 128;
    __shared__ float ss[HH][128];
    for (int q = threadIdx.x; q < HH * 128; q += 256) {
        const int h = q >> 7, ii = q & 127;
        ss[h][ii] = g_ssrc[h * NN + ibase + ii];
    }
    __syncthreads();

    float st[HH], acc[HH];
#pragma unroll
    for (int h = 0; h < HH; h++) { st[h] = g_stgt[h * NN + j]; acc[h] = 0.f; }
    for (int ii = 0; ii < 128; ii += 4) {
        const size_t base = (size_t)(ibase + ii) * NN + j;
        float mrow[4];
        mrow[0] = g_mask[base];
        mrow[1] = g_mask[base + NN];
        mrow[2] = g_mask[base + 2 * NN];
        mrow[3] = g_mask[base + 3 * NN];
#pragma unroll
        for (int q = 0; q < 4; q++) {
#pragma unroll
            for (int h = 0; h < HH; h++) {
                float a = ss[h][ii + q] + st[h];
                a = fmaxf(a, 0.2f * a);
                acc[h] += __expf(a + mrow[q]);
            }
        }
    }
#pragma unroll
    for (int h = 0; h < HH; h++)
        g_part[(blockIdx.y * HH + h) * NN + j] = acc[h];
}

__global__ void k2b_reduce() {
    const int id = blockIdx.x * 256 + threadIdx.x;
    float s = 0.f;
#pragma unroll 8
    for (int c = 0; c < 32; c++) s += g_part[c * HH * NN + id];
    g_denom[id] = 1.0f / s;
}

// ---------------- k3: bf16 mma + ldmatrix + cp.async pipeline --------------
// grid 128 (i-tiles of 32), block 256 = 8 warps = 4 heads x 2 m-halves.
// Per tile: D[32,64] += W[32,64] * P[64,64] per head, bf16 inputs, f32 accum.
struct K3Smem {
    float m[2][32][64];               // mask tile (16 KB)
    __nv_bfloat16 p[2][HH][64][72];   // proj tile; row stride 144B = 9x16B (73.7 KB)
    __nv_bfloat16 w[HH][32][72];      // weights (18.4 KB)
    float st[2][HH][64];
    float rd[2][HH][64];
    float ss[HH][32];
};

__device__ __forceinline__ void k3_issue_tile(K3Smem* S, int ibase, int jt,
                                              int buf, int tid) {
    const int jbase = jt * 64;
    // mask: 32x64 f32 = 512 chunks
#pragma unroll
    for (int c0 = 0; c0 < 512; c0 += 256) {
        const int c = c0 + tid;
        const int r = c >> 4, f4 = (c & 15) << 2;
        cpasync16(&S->m[buf][r][f4], &g_mask[(size_t)(ibase + r) * NN + jbase + f4]);
    }
    // proj: 4 heads x 64 rows x 64 bf16 = 2048 chunks (8 halves each)
#pragma unroll
    for (int c0 = 0; c0 < 2048; c0 += 256) {
        const int c = c0 + tid;
        const int h2 = c >> 9, r = (c >> 3) & 63, c8 = c & 7;
        cpasync16(&S->p[buf][h2][r][c8 * 8],
                  &g_projb[((h2 * NN) + jbase + r) * F_OUT + c8 * 8]);
    }
    if (tid < 64) {
        const int h2 = tid >> 4, j4 = (tid & 15) << 2;
        cpasync16(&S->st[buf][h2][j4], &g_stgt[h2 * NN + jbase + j4]);
    } else if (tid < 128) {
        const int q = tid - 64;
        const int h2 = q >> 4, j4 = (q & 15) << 2;
        cpasync16(&S->rd[buf][h2][j4], &g_denom[h2 * NN + jbase + j4]);
    }
    CP_COMMIT();
}

__global__ void __launch_bounds__(256, 1) k3_mma(float* __restrict__ out) {
    extern __shared__ char smem_raw[];
    K3Smem* S = (K3Smem*)smem_raw;

    const int tid = threadIdx.x;
    const int ibase = blockIdx.x * 32;
    const int wp = tid >> 5;
    const int lane = tid & 31;
    const int h = wp >> 1;             // warp's head
    const int mh = (wp & 1) * 16;      // m-half
    const int g = lane >> 2;
    const int t = lane & 3;
    // producer mapping
    const int c2 = lane;               // col-pair 0..31 (lane)
    const int r4 = wp;                 // row base 0..7 (warp)
    const int jj0 = c2 * 2;

    if (tid < HH * 32) {
        const int h2 = tid >> 5, ii = tid & 31;
        S->ss[h2][ii] = g_ssrc[h2 * NN + ibase + ii];
    }

    // ldmatrix lane bases
    const uint32_t a_base = (uint32_t)__cvta_generic_to_shared(
        &S->w[h][mh + (lane & 15)][(lane >> 4) * 8]);

    float acc[8][4];
#pragma unroll
    for (int nt = 0; nt < 8; nt++)
#pragma unroll
        for (int q = 0; q < 4; q++) acc[nt][q] = 0.f;

    k3_issue_tile(S, ibase, 0, 0, tid);

    for (int jt = 0; jt < 64; jt++) {
        const int buf = jt & 1;
        CP_WAIT0();
        __syncthreads();
        if (jt + 1 < 64) k3_issue_tile(S, ibase, jt + 1, buf ^ 1, tid);

        // ---- produce normalized weights -> bf16 (all smem) ----
#pragma unroll
        for (int h2 = 0; h2 < HH; h2++) {
            const float st0 = S->st[buf][h2][jj0];
            const float st1 = S->st[buf][h2][jj0 + 1];
            const float rd0 = S->rd[buf][h2][jj0];
            const float rd1 = S->rd[buf][h2][jj0 + 1];
#pragma unroll
            for (int q = 0; q < 4; q++) {
                const int ii = r4 + q * 8;
                const float2 mm = *(const float2*)&S->m[buf][ii][jj0];
                const float ssv = S->ss[h2][ii];
                float a0 = ssv + st0; a0 = fmaxf(a0, 0.2f * a0);
                float a1 = ssv + st1; a1 = fmaxf(a1, 0.2f * a1);
                const float e0 = __expf(a0 + mm.x) * rd0;
                const float e1 = __expf(a1 + mm.y) * rd1;
                *(__nv_bfloat162*)&S->w[h2][ii][jj0] =
                    __floats2bfloat162_rn(e0, e1);
            }
        }
        __syncthreads();

        // ---- bf16 tensor contraction: 4 k-steps x 4 n-blocks ----
        const uint32_t p_base = (uint32_t)__cvta_generic_to_shared(
            &S->p[buf][h][lane & 15][(lane >> 4) * 8]);
#pragma unroll
        for (int ks = 0; ks < 4; ks++) {
            uint32_t A0, A1, A2, A3;
            LDSM_X4(A0, A1, A2, A3, a_base + ks * 32);
#pragma unroll
            for (int nb = 0; nb < 4; nb++) {
                uint32_t B0, B1, B2, B3;
                LDSM_X4T(B0, B1, B2, B3, p_base + ks * 16 * 144 + nb * 32);
                mma_bf16(acc[2 * nb], A0, A1, A2, A3, B0, B1);
                mma_bf16(acc[2 * nb + 1], A0, A1, A2, A3, B2, B3);
            }
        }
    }

    // epilogue: + skip, ELU, write
#pragma unroll
    for (int nt = 0; nt < 8; nt++) {
        const int f0 = nt * 8 + t * 2;
        const int n0 = ibase + mh + g;
        const int n1 = n0 + 8;
#pragma unroll
        for (int q = 0; q < 4; q++) {
            const int n = (q >= 2) ? n1 : n0;
            const int f = f0 + (q & 1);
            const int o = n * (HH * F_OUT) + h * F_OUT + f;
            float v = acc[nt][q] + g_skip[o];
            v = (v > 0.f) ? v : (__expf(v) - 1.f);
            out[o] = v;
        }
    }
}

// ---------------- launch ---------------------------------------------------
extern "C" void kernel_launch(void* const* d_in, const int* in_sizes, int n_in,
                              void* d_out, int out_size) {
    const float* nodes = (const float*)d_in[0];
    const float* deg   = (const float*)d_in[1];
    const float* bond  = (const float*)d_in[3];
    const float* pp    = (const float*)d_in[4];
    const float* wsrc  = (const float*)d_in[5];
    const float* wtgt  = (const float*)d_in[6];
    const float* skw   = (const float*)d_in[7];
    const int*   cut   = (const int*)d_in[8];

    float* out    = (float*)d_out;
    float* ln_out = (float*)d_out + (size_t)NN * HH * F_OUT;

    const int k3_smem = (int)sizeof(K3Smem);
    cudaFuncSetAttribute(k3_mma, cudaFuncAttributeMaxDynamicSharedMemorySize, k3_smem);

    k0_fused<<<256, 256>>>(nodes, pp, skw, wsrc, wtgt);
    k1_mask_ln<<<NN, 512>>>(deg, bond, cut, ln_out);
    k2_colsum<<<dim3(16, 32), 256>>>();
    k2b_reduce<<<64, 256>>>();
    k3_mma<<<128, 256, k3_smem>>>(out);
}

// round 5
// speedup vs baseline: 5.0201x; 1.1108x over previous
#include <cuda_runtime.h>
#include <cuda_bf16.h>
#include <math.h>
#include <stdint.h>

#define NN 4096
#define F_IN 128
#define F_OUT 64
#define HH 4
#define NEG_INF -1e9f
#define LN_EPS 1e-5f

// ---------------- scratch (device globals: allocation-free) ----------------
__device__ float g_mask[(size_t)NN * NN];               // 64 MB
__device__ __nv_bfloat16 g_projb[HH * NN * F_OUT];      // 2 MB  bf16 [h][n][o]
__device__ float g_skip[NN * HH * F_OUT];               // 4 MB
__device__ float g_ssrc[HH * NN];
__device__ float g_stgt[HH * NN];
__device__ float g_part[32 * HH * NN];                  // deterministic partial col-sums
__device__ float g_nld[HH * NN];                        // -ln(denom)
__device__ float g_pout[2][NN * HH * F_OUT];            // 32 MB j-split partials

// ---------------- asm helpers ----------------------------------------------
__device__ __forceinline__ void cpasync16(void* s, const void* g) {
    uint32_t sa = (uint32_t)__cvta_generic_to_shared(s);
    asm volatile("cp.async.cg.shared.global [%0], [%1], 16;" :: "r"(sa), "l"(g));
}
#define CP_COMMIT() asm volatile("cp.async.commit_group;")
#define CP_WAIT0()  asm volatile("cp.async.wait_group 0;")

#define LDSM_X4(r0, r1, r2, r3, a) \
    asm volatile("ldmatrix.sync.aligned.m8n8.x4.shared.b16 {%0,%1,%2,%3}, [%4];" \
                 : "=r"(r0), "=r"(r1), "=r"(r2), "=r"(r3) : "r"(a))
#define LDSM_X4T(r0, r1, r2, r3, a) \
    asm volatile("ldmatrix.sync.aligned.m8n8.x4.trans.shared.b16 {%0,%1,%2,%3}, [%4];" \
                 : "=r"(r0), "=r"(r1), "=r"(r2), "=r"(r3) : "r"(a))

__device__ __forceinline__ void mma_bf16(float* c, uint32_t a0, uint32_t a1,
                                         uint32_t a2, uint32_t a3,
                                         uint32_t b0, uint32_t b1) {
    asm volatile(
        "mma.sync.aligned.m16n8k16.row.col.f32.bf16.bf16.f32 "
        "{%0,%1,%2,%3}, {%4,%5,%6,%7}, {%8,%9}, {%0,%1,%2,%3};"
        : "+f"(c[0]), "+f"(c[1]), "+f"(c[2]), "+f"(c[3])
        : "r"(a0), "r"(a1), "r"(a2), "r"(a3), "r"(b0), "r"(b1));
}

// ---------------- k0: fused proj(bf16) + scores + skip ---------------------
__global__ void k0_fused(const float* __restrict__ nodes,
                         const float* __restrict__ pp,
                         const float* __restrict__ skw,
                         const float* __restrict__ wsrc,
                         const float* __restrict__ wtgt) {
    __shared__ float xs[16][F_IN];
    __shared__ float red[2][2][HH][16];
    const int nbase = blockIdx.x * 16;
    const int tid = threadIdx.x;
    for (int q = tid; q < 16 * F_IN; q += 256)
        xs[q >> 7][q & 127] = nodes[nbase * F_IN + q];
    __syncthreads();

    const int h = tid >> 6, o = tid & 63;
    const int lane = tid & 31, half = (tid >> 5) & 1;

    float acc[16];
#pragma unroll
    for (int k = 0; k < 16; k++) acc[k] = 0.f;
    for (int f = 0; f < F_IN; f++) {
        float w = pp[h * F_IN * F_OUT + f * F_OUT + o];
#pragma unroll
        for (int k = 0; k < 16; k++) acc[k] += xs[k][f] * w;
    }
#pragma unroll
    for (int k = 0; k < 16; k++)
        g_projb[(h * NN + nbase + k) * F_OUT + o] = __float2bfloat16_rn(acc[k]);

    {
        const float ws = wsrc[h * F_OUT + o];
        const float wt = wtgt[h * F_OUT + o];
#pragma unroll
        for (int k = 0; k < 16; k++) {
            float s = acc[k] * ws, t = acc[k] * wt;
#pragma unroll
            for (int off = 16; off; off >>= 1) {
                s += __shfl_down_sync(0xffffffffu, s, off);
                t += __shfl_down_sync(0xffffffffu, t, off);
            }
            if (lane == 0) { red[0][half][h][k] = s; red[1][half][h][k] = t; }
        }
    }
    __syncthreads();
    if (tid < 128) {
        const int h2 = tid >> 5, k = (tid >> 1) & 15, sel = tid & 1;
        const float v = red[sel][0][h2][k] + red[sel][1][h2][k];
        if (sel == 0) g_ssrc[h2 * NN + nbase + k] = v;
        else          g_stgt[h2 * NN + nbase + k] = v;
    }

#pragma unroll
    for (int k = 0; k < 16; k++) acc[k] = 0.f;
    for (int f = 0; f < F_IN; f++) {
        float w = skw[tid * F_IN + f];
#pragma unroll
        for (int k = 0; k < 16; k++) acc[k] += xs[k][f] * w;
    }
#pragma unroll
    for (int k = 0; k < 16; k++)
        g_skip[(nbase + k) * (HH * F_OUT) + tid] = acc[k];
}

// ---------------- k1: mask + row LayerNorm (512 thr, streaming) ------------
__global__ void k1_mask_ln(const float* __restrict__ deg,
                           const float* __restrict__ bond,
                           const int* __restrict__ cutoff_p,
                           float* __restrict__ ln_out) {
    const int i = blockIdx.x;
    const int tid = threadIdx.x;
    const float cut = (float)(*cutoff_p);
    const size_t row = (size_t)i * NN;

    float4 m4[2];
    float s = 0.f, s2 = 0.f;
#pragma unroll
    for (int k = 0; k < 2; k++) {
        const int j4 = (k * 512 + tid) * 4;
        const float4 d4 = __ldcs((const float4*)&deg[row + j4]);
        const float4 b4 = __ldcs((const float4*)&bond[row + j4]);
        float4 m;
        float w;
        w = d4.x + b4.x; m.x = (w > 0.f) ? w : ((b4.x > cut) ? (b4.x + w) : NEG_INF);
        w = d4.y + b4.y; m.y = (w > 0.f) ? w : ((b4.y > cut) ? (b4.y + w) : NEG_INF);
        w = d4.z + b4.z; m.z = (w > 0.f) ? w : ((b4.z > cut) ? (b4.z + w) : NEG_INF);
        w = d4.w + b4.w; m.w = (w > 0.f) ? w : ((b4.w > cut) ? (b4.w + w) : NEG_INF);
        m4[k] = m;
        *(float4*)&g_mask[row + j4] = m;
        s  += (m.x + m.y) + (m.z + m.w);
        s2 += (m.x * m.x + m.y * m.y) + (m.z * m.z + m.w * m.w);
    }
    __shared__ float rs[16], rs2[16];
    const int lane = tid & 31, wp = tid >> 5;
#pragma unroll
    for (int off = 16; off; off >>= 1) {
        s  += __shfl_down_sync(0xffffffffu, s, off);
        s2 += __shfl_down_sync(0xffffffffu, s2, off);
    }
    if (lane == 0) { rs[wp] = s; rs2[wp] = s2; }
    __syncthreads();
    if (wp == 0) {
        float a  = (lane < 16) ? rs[lane] : 0.f;
        float a2 = (lane < 16) ? rs2[lane] : 0.f;
#pragma unroll
        for (int off = 8; off; off >>= 1) {
            a  += __shfl_down_sync(0xffffffffu, a, off);
            a2 += __shfl_down_sync(0xffffffffu, a2, off);
        }
        if (lane == 0) { rs[0] = a; rs2[0] = a2; }
    }
    __syncthreads();
    const float mu  = rs[0] * (1.0f / NN);
    const float var = fmaxf(rs2[0] * (1.0f / NN) - mu * mu, 0.f);
    const float rstd = 1.0f / sqrtf(var + LN_EPS);
#pragma unroll
    for (int k = 0; k < 2; k++) {
        const int j4 = (k * 512 + tid) * 4;
        float4 o4;
        o4.x = (m4[k].x - mu) * rstd;
        o4.y = (m4[k].y - mu) * rstd;
        o4.z = (m4[k].z - mu) * rstd;
        o4.w = (m4[k].w - mu) * rstd;
        __stcs((float4*)&ln_out[row + j4], o4);
    }
}

// ---------------- k2: column-wise exp partial sums (deterministic) ---------
__global__ void k2_colsum() {
    const int j = blockIdx.x * 256 + threadIdx.x;
    const int ibase = blockIdx.y * 128;
    __shared__ float ss[HH][128];
    for (int q = threadIdx.x; q < HH * 128; q += 256) {
        const int h = q >> 7, ii = q & 127;
        ss[h][ii] = g_ssrc[h * NN + ibase + ii];
    }
    __syncthreads();

    float st[HH], acc[HH];
#pragma unroll
    for (int h = 0; h < HH; h++) { st[h] = g_stgt[h * NN + j]; acc[h] = 0.f; }
    for (int ii = 0; ii < 128; ii += 4) {
        const size_t base = (size_t)(ibase + ii) * NN + j;
        float mrow[4];
        mrow[0] = g_mask[base];
        mrow[1] = g_mask[base + NN];
        mrow[2] = g_mask[base + 2 * NN];
        mrow[3] = g_mask[base + 3 * NN];
#pragma unroll
        for (int q = 0; q < 4; q++) {
#pragma unroll
            for (int h = 0; h < HH; h++) {
                float a = ss[h][ii + q] + st[h];
                a = fmaxf(a, 0.2f * a);
                acc[h] += __expf(a + mrow[q]);
            }
        }
    }
#pragma unroll
    for (int h = 0; h < HH; h++)
        g_part[(blockIdx.y * HH + h) * NN + j] = acc[h];
}

__global__ void k2b_reduce() {
    const int id = blockIdx.x * 256 + threadIdx.x;
    float s = 0.f;
#pragma unroll
    for (int c = 0; c < 32; c++) s += g_part[c * HH * NN + id];
    g_nld[id] = -__logf(s);
}

// ---------------- k3: bf16 mma, j-split, 2 blocks/SM -----------------------
// grid (128, 2): x = i-tile of 32 rows, y = j-half. block 256 = 8 warps.
struct K3Smem {
    float m[2][32][64];               // mask tile (16 KB)
    __nv_bfloat16 p[2][HH][64][72];   // proj tile; row stride 144B (73.7 KB)
    __nv_bfloat16 w[HH][32][72];      // weights (18.4 KB)
    float st[2][HH][64];
    float ld[2][HH][64];              // -ln(denom)
    float ss[HH][32];
};

__device__ __forceinline__ void k3_issue_tile(K3Smem* S, int ibase, int jt,
                                              int buf, int tid) {
    const int jbase = jt * 64;
#pragma unroll
    for (int c0 = 0; c0 < 512; c0 += 256) {
        const int c = c0 + tid;
        const int r = c >> 4, f4 = (c & 15) << 2;
        cpasync16(&S->m[buf][r][f4], &g_mask[(size_t)(ibase + r) * NN + jbase + f4]);
    }
#pragma unroll
    for (int c0 = 0; c0 < 2048; c0 += 256) {
        const int c = c0 + tid;
        const int h2 = c >> 9, r = (c >> 3) & 63, c8 = c & 7;
        cpasync16(&S->p[buf][h2][r][c8 * 8],
                  &g_projb[((h2 * NN) + jbase + r) * F_OUT + c8 * 8]);
    }
    if (tid < 64) {
        const int h2 = tid >> 4, j4 = (tid & 15) << 2;
        cpasync16(&S->st[buf][h2][j4], &g_stgt[h2 * NN + jbase + j4]);
    } else if (tid < 128) {
        const int q = tid - 64;
        const int h2 = q >> 4, j4 = (q & 15) << 2;
        cpasync16(&S->ld[buf][h2][j4], &g_nld[h2 * NN + jbase + j4]);
    }
    CP_COMMIT();
}

__global__ void __launch_bounds__(256, 1) k3_mma(void) {
    extern __shared__ char smem_raw[];
    K3Smem* S = (K3Smem*)smem_raw;

    const int tid = threadIdx.x;
    const int ibase = blockIdx.x * 32;
    const int split = blockIdx.y;
    const int jt0 = split * 32;
    const int wp = tid >> 5;
    const int lane = tid & 31;
    const int h = wp >> 1;
    const int mh = (wp & 1) * 16;
    const int g = lane >> 2;
    const int t = lane & 3;
    const int r4 = wp;
    const int jj0 = lane * 2;

    if (tid < HH * 32) {
        const int h2 = tid >> 5, ii = tid & 31;
        S->ss[h2][ii] = g_ssrc[h2 * NN + ibase + ii];
    }

    const uint32_t a_base = (uint32_t)__cvta_generic_to_shared(
        &S->w[h][mh + (lane & 15)][(lane >> 4) * 8]);

    float acc[8][4];
#pragma unroll
    for (int nt = 0; nt < 8; nt++)
#pragma unroll
        for (int q = 0; q < 4; q++) acc[nt][q] = 0.f;

    k3_issue_tile(S, ibase, jt0, 0, tid);

    for (int jx = 0; jx < 32; jx++) {
        const int buf = jx & 1;
        CP_WAIT0();
        __syncthreads();
        if (jx + 1 < 32) k3_issue_tile(S, ibase, jt0 + jx + 1, buf ^ 1, tid);

        // ---- produce normalized weights -> bf16 ----
        float stv0[HH], stv1[HH], ldv0[HH], ldv1[HH];
#pragma unroll
        for (int h2 = 0; h2 < HH; h2++) {
            const float2 t2 = *(const float2*)&S->st[buf][h2][jj0];
            const float2 l2 = *(const float2*)&S->ld[buf][h2][jj0];
            stv0[h2] = t2.x; stv1[h2] = t2.y;
            ldv0[h2] = l2.x; ldv1[h2] = l2.y;
        }
#pragma unroll
        for (int q = 0; q < 4; q++) {
            const int ii = r4 + q * 8;
            const float2 mm = *(const float2*)&S->m[buf][ii][jj0];
#pragma unroll
            for (int h2 = 0; h2 < HH; h2++) {
                const float ssv = S->ss[h2][ii];
                float a0 = ssv + stv0[h2]; a0 = fmaxf(a0, 0.2f * a0);
                float a1 = ssv + stv1[h2]; a1 = fmaxf(a1, 0.2f * a1);
                const float e0 = __expf(a0 + mm.x + ldv0[h2]);
                const float e1 = __expf(a1 + mm.y + ldv1[h2]);
                *(__nv_bfloat162*)&S->w[h2][ii][jj0] =
                    __floats2bfloat162_rn(e0, e1);
            }
        }
        __syncthreads();

        // ---- bf16 tensor contraction ----
        const uint32_t p_base = (uint32_t)__cvta_generic_to_shared(
            &S->p[buf][h][lane & 15][(lane >> 4) * 8]);
#pragma unroll
        for (int ks = 0; ks < 4; ks++) {
            uint32_t A0, A1, A2, A3;
            LDSM_X4(A0, A1, A2, A3, a_base + ks * 32);
#pragma unroll
            for (int nb = 0; nb < 4; nb++) {
                uint32_t B0, B1, B2, B3;
                LDSM_X4T(B0, B1, B2, B3, p_base + ks * 16 * 144 + nb * 32);
                mma_bf16(acc[2 * nb], A0, A1, A2, A3, B0, B1);
                mma_bf16(acc[2 * nb + 1], A0, A1, A2, A3, B2, B3);
            }
        }
    }

    // partial writeout (no skip/ELU here)
    float* po = g_pout[split];
#pragma unroll
    for (int nt = 0; nt < 8; nt++) {
        const int f0 = nt * 8 + t * 2;
        const int n0 = ibase + mh + g;
        const int n1 = n0 + 8;
#pragma unroll
        for (int q = 0; q < 4; q++) {
            const int n = (q >= 2) ? n1 : n0;
            const int f = f0 + (q & 1);
            po[n * (HH * F_OUT) + h * F_OUT + f] = acc[nt][q];
        }
    }
}

// ---------------- k4: combine splits + skip + ELU --------------------------
__global__ void k4_combine(float* __restrict__ out) {
    const int i4 = (blockIdx.x * 256 + threadIdx.x) * 4;
    const float4 p0 = *(const float4*)&g_pout[0][i4];
    const float4 p1 = *(const float4*)&g_pout[1][i4];
    const float4 sk = *(const float4*)&g_skip[i4];
    float4 o;
    float v;
    v = p0.x + p1.x + sk.x; o.x = (v > 0.f) ? v : (__expf(v) - 1.f);
    v = p0.y + p1.y + sk.y; o.y = (v > 0.f) ? v : (__expf(v) - 1.f);
    v = p0.z + p1.z + sk.z; o.z = (v > 0.f) ? v : (__expf(v) - 1.f);
    v = p0.w + p1.w + sk.w; o.w = (v > 0.f) ? v : (__expf(v) - 1.f);
    *(float4*)&out[i4] = o;
}

// ---------------- launch ---------------------------------------------------
extern "C" void kernel_launch(void* const* d_in, const int* in_sizes, int n_in,
                              void* d_out, int out_size) {
    const float* nodes = (const float*)d_in[0];
    const float* deg   = (const float*)d_in[1];
    const float* bond  = (const float*)d_in[3];
    const float* pp    = (const float*)d_in[4];
    const float* wsrc  = (const float*)d_in[5];
    const float* wtgt  = (const float*)d_in[6];
    const float* skw   = (const float*)d_in[7];
    const int*   cut   = (const int*)d_in[8];

    float* out    = (float*)d_out;
    float* ln_out = (float*)d_out + (size_t)NN * HH * F_OUT;

    const int k3_smem = (int)sizeof(K3Smem);
    cudaFuncSetAttribute(k3_mma, cudaFuncAttributeMaxDynamicSharedMemorySize, k3_smem);

    k0_fused<<<256, 256>>>(nodes, pp, skw, wsrc, wtgt);
    k1_mask_ln<<<NN, 512>>>(deg, bond, cut, ln_out);
    k2_colsum<<<dim3(16, 32), 256>>>();
    k2b_reduce<<<64, 256>>>();
    k3_mma<<<dim3(128, 2), 256, k3_smem>>>();
    k4_combine<<<1024, 256>>>(out);
}

// round 6
// speedup vs baseline: 5.0465x; 1.0053x over previous
#include <cuda_runtime.h>
#include <cuda_bf16.h>
#include <math.h>
#include <stdint.h>

#define NN 4096
#define F_IN 128
#define F_OUT 64
#define HH 4
#define NEG_INF -1e9f
#define LN_EPS 1e-5f
#define NTILE 64            // j-tiles of 64 columns

// ---------------- scratch (device globals: allocation-free) ----------------
__device__ float g_mask[(size_t)NN * NN];                      // 64 MB
__device__ __align__(16) __nv_bfloat16 g_projp[HH][NTILE][64][72];  // padded proj tiles
__device__ float g_skip[NN * HH * F_OUT];                      // 4 MB
__device__ float g_ssrc[HH * NN];
__device__ float g_stgt[HH * NN];
__device__ __align__(16) float g_stgt2[NTILE][HH][64];         // tiled copy for k3
__device__ float g_part[32 * HH * NN];                         // partial col-sums
__device__ __align__(16) float g_nld2[NTILE][HH][64];          // -ln(denom), tiled
__device__ float g_pout[2][NN * HH * F_OUT];                   // j-split partials

// ---------------- asm helpers ----------------------------------------------
__device__ __forceinline__ uint32_t smem_u32(const void* p) {
    return (uint32_t)__cvta_generic_to_shared(p);
}
__device__ __forceinline__ void bulkcp(void* s, const void* g, int bytes,
                                       uint32_t mbar) {
    asm volatile(
        "cp.async.bulk.shared::cta.global.mbarrier::complete_tx::bytes "
        "[%0], [%1], %2, [%3];"
        :: "r"(smem_u32(s)), "l"(g), "r"(bytes), "r"(mbar) : "memory");
}
__device__ __forceinline__ void mbar_init(uint32_t mbar, uint32_t cnt) {
    asm volatile("mbarrier.init.shared.b64 [%0], %1;" :: "r"(mbar), "r"(cnt) : "memory");
}
__device__ __forceinline__ void mbar_expect_tx(uint32_t mbar, uint32_t bytes) {
    asm volatile("mbarrier.arrive.expect_tx.shared.b64 _, [%0], %1;"
                 :: "r"(mbar), "r"(bytes) : "memory");
}
__device__ __forceinline__ void mbar_wait(uint32_t mbar, uint32_t parity) {
    asm volatile(
        "{\n\t.reg .pred P1;\n\t"
        "WAIT_LOOP_%=:\n\t"
        "mbarrier.try_wait.parity.acquire.cta.shared::cta.b64 P1, [%0], %1, 0x989680;\n\t"
        "@P1 bra.uni WAIT_DONE_%=;\n\t"
        "bra.uni WAIT_LOOP_%=;\n\t"
        "WAIT_DONE_%=:\n\t}"
        :: "r"(mbar), "r"(parity) : "memory");
}

#define LDSM_X4(r0, r1, r2, r3, a) \
    asm volatile("ldmatrix.sync.aligned.m8n8.x4.shared.b16 {%0,%1,%2,%3}, [%4];" \
                 : "=r"(r0), "=r"(r1), "=r"(r2), "=r"(r3) : "r"(a))
#define LDSM_X4T(r0, r1, r2, r3, a) \
    asm volatile("ldmatrix.sync.aligned.m8n8.x4.trans.shared.b16 {%0,%1,%2,%3}, [%4];" \
                 : "=r"(r0), "=r"(r1), "=r"(r2), "=r"(r3) : "r"(a))

__device__ __forceinline__ void mma_bf16(float* c, uint32_t a0, uint32_t a1,
                                         uint32_t a2, uint32_t a3,
                                         uint32_t b0, uint32_t b1) {
    asm volatile(
        "mma.sync.aligned.m16n8k16.row.col.f32.bf16.bf16.f32 "
        "{%0,%1,%2,%3}, {%4,%5,%6,%7}, {%8,%9}, {%0,%1,%2,%3};"
        : "+f"(c[0]), "+f"(c[1]), "+f"(c[2]), "+f"(c[3])
        : "r"(a0), "r"(a1), "r"(a2), "r"(a3), "r"(b0), "r"(b1));
}

// ---------------- k0: fused proj(bf16) + scores + skip ---------------------
__global__ void k0_fused(const float* __restrict__ nodes,
                         const float* __restrict__ pp,
                         const float* __restrict__ skw,
                         const float* __restrict__ wsrc,
                         const float* __restrict__ wtgt) {
    __shared__ float xs[16][F_IN];
    __shared__ float red[2][2][HH][16];
    const int nbase = blockIdx.x * 16;
    const int tid = threadIdx.x;
    for (int q = tid; q < 16 * F_IN; q += 256)
        xs[q >> 7][q & 127] = nodes[nbase * F_IN + q];
    __syncthreads();

    const int h = tid >> 6, o = tid & 63;
    const int lane = tid & 31, half = (tid >> 5) & 1;
    const int jt = nbase >> 6, rbase = nbase & 63;

    float acc[16];
#pragma unroll
    for (int k = 0; k < 16; k++) acc[k] = 0.f;
    for (int f = 0; f < F_IN; f++) {
        float w = pp[h * F_IN * F_OUT + f * F_OUT + o];
#pragma unroll
        for (int k = 0; k < 16; k++) acc[k] += xs[k][f] * w;
    }
#pragma unroll
    for (int k = 0; k < 16; k++)
        g_projp[h][jt][rbase + k][o] = __float2bfloat16_rn(acc[k]);

    {
        const float ws = wsrc[h * F_OUT + o];
        const float wt = wtgt[h * F_OUT + o];
#pragma unroll
        for (int k = 0; k < 16; k++) {
            float s = acc[k] * ws, t = acc[k] * wt;
#pragma unroll
            for (int off = 16; off; off >>= 1) {
                s += __shfl_down_sync(0xffffffffu, s, off);
                t += __shfl_down_sync(0xffffffffu, t, off);
            }
            if (lane == 0) { red[0][half][h][k] = s; red[1][half][h][k] = t; }
        }
    }
    __syncthreads();
    if (tid < 128) {
        const int h2 = tid >> 5, k = (tid >> 1) & 15, sel = tid & 1;
        const float v = red[sel][0][h2][k] + red[sel][1][h2][k];
        const int n = nbase + k;
        if (sel == 0) g_ssrc[h2 * NN + n] = v;
        else { g_stgt[h2 * NN + n] = v; g_stgt2[n >> 6][h2][n & 63] = v; }
    }

#pragma unroll
    for (int k = 0; k < 16; k++) acc[k] = 0.f;
    for (int f = 0; f < F_IN; f++) {
        float w = skw[tid * F_IN + f];
#pragma unroll
        for (int k = 0; k < 16; k++) acc[k] += xs[k][f] * w;
    }
#pragma unroll
    for (int k = 0; k < 16; k++)
        g_skip[(nbase + k) * (HH * F_OUT) + tid] = acc[k];
}

// ---------------- k1: mask + row LayerNorm (512 thr, streaming) ------------
__global__ void k1_mask_ln(const float* __restrict__ deg,
                           const float* __restrict__ bond,
                           const int* __restrict__ cutoff_p,
                           float* __restrict__ ln_out) {
    const int i = blockIdx.x;
    const int tid = threadIdx.x;
    const float cut = (float)(*cutoff_p);
    const size_t row = (size_t)i * NN;

    float4 m4[2];
    float s = 0.f, s2 = 0.f;
#pragma unroll
    for (int k = 0; k < 2; k++) {
        const int j4 = (k * 512 + tid) * 4;
        const float4 d4 = __ldcs((const float4*)&deg[row + j4]);
        const float4 b4 = __ldcs((const float4*)&bond[row + j4]);
        float4 m;
        float w;
        w = d4.x + b4.x; m.x = (w > 0.f) ? w : ((b4.x > cut) ? (b4.x + w) : NEG_INF);
        w = d4.y + b4.y; m.y = (w > 0.f) ? w : ((b4.y > cut) ? (b4.y + w) : NEG_INF);
        w = d4.z + b4.z; m.z = (w > 0.f) ? w : ((b4.z > cut) ? (b4.z + w) : NEG_INF);
        w = d4.w + b4.w; m.w = (w > 0.f) ? w : ((b4.w > cut) ? (b4.w + w) : NEG_INF);
        m4[k] = m;
        *(float4*)&g_mask[row + j4] = m;
        s  += (m.x + m.y) + (m.z + m.w);
        s2 += (m.x * m.x + m.y * m.y) + (m.z * m.z + m.w * m.w);
    }
    __shared__ float rs[16], rs2[16];
    const int lane = tid & 31, wp = tid >> 5;
#pragma unroll
    for (int off = 16; off; off >>= 1) {
        s  += __shfl_down_sync(0xffffffffu, s, off);
        s2 += __shfl_down_sync(0xffffffffu, s2, off);
    }
    if (lane == 0) { rs[wp] = s; rs2[wp] = s2; }
    __syncthreads();
    if (wp == 0) {
        float a  = (lane < 16) ? rs[lane] : 0.f;
        float a2 = (lane < 16) ? rs2[lane] : 0.f;
#pragma unroll
        for (int off = 8; off; off >>= 1) {
            a  += __shfl_down_sync(0xffffffffu, a, off);
            a2 += __shfl_down_sync(0xffffffffu, a2, off);
        }
        if (lane == 0) { rs[0] = a; rs2[0] = a2; }
    }
    __syncthreads();
    const float mu  = rs[0] * (1.0f / NN);
    const float var = fmaxf(rs2[0] * (1.0f / NN) - mu * mu, 0.f);
    const float rstd = 1.0f / sqrtf(var + LN_EPS);
#pragma unroll
    for (int k = 0; k < 2; k++) {
        const int j4 = (k * 512 + tid) * 4;
        float4 o4;
        o4.x = (m4[k].x - mu) * rstd;
        o4.y = (m4[k].y - mu) * rstd;
        o4.z = (m4[k].z - mu) * rstd;
        o4.w = (m4[k].w - mu) * rstd;
        __stcs((float4*)&ln_out[row + j4], o4);
    }
}

// ---------------- k2: column-wise exp partial sums (deterministic) ---------
__global__ void k2_colsum() {
    const int j = blockIdx.x * 256 + threadIdx.x;
    const int ibase = blockIdx.y * 128;
    __shared__ float ss[HH][128];
    for (int q = threadIdx.x; q < HH * 128; q += 256) {
        const int h = q >> 7, ii = q & 127;
        ss[h][ii] = g_ssrc[h * NN + ibase + ii];
    }
    __syncthreads();

    float st[HH], acc[HH];
#pragma unroll
    for (int h = 0; h < HH; h++) { st[h] = g_stgt[h * NN + j]; acc[h] = 0.f; }
    for (int ii = 0; ii < 128; ii += 4) {
        const size_t base = (size_t)(ibase + ii) * NN + j;
        float mrow[4];
        mrow[0] = g_mask[base];
        mrow[1] = g_mask[base + NN];
        mrow[2] = g_mask[base + 2 * NN];
        mrow[3] = g_mask[base + 3 * NN];
#pragma unroll
        for (int q = 0; q < 4; q++) {
#pragma unroll
            for (int h = 0; h < HH; h++) {
                float a = ss[h][ii + q] + st[h];
                a = fmaxf(a, 0.2f * a);
                acc[h] += __expf(a + mrow[q]);
            }
        }
    }
#pragma unroll
    for (int h = 0; h < HH; h++)
        g_part[(blockIdx.y * HH + h) * NN + j] = acc[h];
}

__global__ void k2b_reduce() {
    const int id = blockIdx.x * 256 + threadIdx.x;   // h*NN + j
    float s = 0.f;
#pragma unroll
    for (int c = 0; c < 32; c++) s += g_part[c * HH * NN + id];
    const int h = id >> 12, j = id & (NN - 1);
    g_nld2[j >> 6][h][j & 63] = -__logf(s);
}

// ---------------- k3: bf16 mma + TMA-bulk staging, j-split -----------------
// grid (128, 2): x = i-tile of 32 rows, y = j-half. block 256 = 8 warps.
struct K3Smem {
    __nv_bfloat16 p[2][HH][64][72];   // proj tile (bulk-copied, padding baked) 73.7KB
    float m[2][32][64];               // mask tile 16KB
    float st[2][HH][64];
    float ld[2][HH][64];              // -ln(denom)
    __nv_bfloat16 w[HH][32][72];      // weights 18.4KB
    float ss[HH][32];
    unsigned long long mbar[2];
};
#define K3_TX_BYTES (32 * 256 + HH * 9216 + 1024 + 1024)   // 47104

__device__ __forceinline__ void k3_issue(K3Smem* S, int ibase, int jt, int buf,
                                         uint32_t mb) {
    mbar_expect_tx(mb, K3_TX_BYTES);
    const int jbase = jt * 64;
#pragma unroll 4
    for (int r = 0; r < 32; r++)
        bulkcp(&S->m[buf][r][0], &g_mask[(size_t)(ibase + r) * NN + jbase], 256, mb);
#pragma unroll
    for (int h2 = 0; h2 < HH; h2++)
        bulkcp(&S->p[buf][h2][0][0], &g_projp[h2][jt][0][0], 9216, mb);
    bulkcp(&S->st[buf][0][0], &g_stgt2[jt][0][0], 1024, mb);
    bulkcp(&S->ld[buf][0][0], &g_nld2[jt][0][0], 1024, mb);
}

__global__ void __launch_bounds__(256) k3_mma(void) {
    extern __shared__ char smem_raw[];
    K3Smem* S = (K3Smem*)smem_raw;

    const int tid = threadIdx.x;
    const int ibase = blockIdx.x * 32;
    const int split = blockIdx.y;
    const int jt0 = split * 32;
    const int wp = tid >> 5;
    const int lane = tid & 31;
    const int h = wp >> 1;
    const int mh = (wp & 1) * 16;
    const int g = lane >> 2;
    const int t = lane & 3;
    const int r4 = wp;
    const int jj0 = lane * 2;

    const uint32_t mb0 = smem_u32(&S->mbar[0]);
    const uint32_t mb1 = smem_u32(&S->mbar[1]);

    if (tid < HH * 32) {
        const int h2 = tid >> 5, ii = tid & 31;
        S->ss[h2][ii] = g_ssrc[h2 * NN + ibase + ii];
    }
    if (tid == 0) {
        mbar_init(mb0, 1);
        mbar_init(mb1, 1);
        asm volatile("fence.proxy.async.shared::cta;" ::: "memory");
    }
    __syncthreads();
    if (tid == 0) {
        k3_issue(S, ibase, jt0 + 0, 0, mb0);
        k3_issue(S, ibase, jt0 + 1, 1, mb1);
    }

    const uint32_t a_base = smem_u32(&S->w[h][mh + (lane & 15)][(lane >> 4) * 8]);

    float acc[8][4];
#pragma unroll
    for (int nt = 0; nt < 8; nt++)
#pragma unroll
        for (int q = 0; q < 4; q++) acc[nt][q] = 0.f;

    for (int jx = 0; jx < 32; jx++) {
        const int buf = jx & 1;
        mbar_wait(buf ? mb1 : mb0, (jx >> 1) & 1);

        // ---- produce normalized weights -> bf16 ----
        float stv0[HH], stv1[HH], ldv0[HH], ldv1[HH];
#pragma unroll
        for (int h2 = 0; h2 < HH; h2++) {
            const float2 t2 = *(const float2*)&S->st[buf][h2][jj0];
            const float2 l2 = *(const float2*)&S->ld[buf][h2][jj0];
            stv0[h2] = t2.x; stv1[h2] = t2.y;
            ldv0[h2] = l2.x; ldv1[h2] = l2.y;
        }
#pragma unroll
        for (int q = 0; q < 4; q++) {
            const int ii = r4 + q * 8;
            const float2 mm = *(const float2*)&S->m[buf][ii][jj0];
#pragma unroll
            for (int h2 = 0; h2 < HH; h2++) {
                const float ssv = S->ss[h2][ii];
                float a0 = ssv + stv0[h2]; a0 = fmaxf(a0, 0.2f * a0);
                float a1 = ssv + stv1[h2]; a1 = fmaxf(a1, 0.2f * a1);
                const float e0 = __expf(a0 + mm.x + ldv0[h2]);
                const float e1 = __expf(a1 + mm.y + ldv1[h2]);
                *(__nv_bfloat162*)&S->w[h2][ii][jj0] =
                    __floats2bfloat162_rn(e0, e1);
            }
        }
        __syncthreads();

        // ---- bf16 tensor contraction ----
        const uint32_t p_base = smem_u32(&S->p[buf][h][lane & 15][(lane >> 4) * 8]);
#pragma unroll
        for (int ks = 0; ks < 4; ks++) {
            uint32_t A0, A1, A2, A3;
            LDSM_X4(A0, A1, A2, A3, a_base + ks * 32);
#pragma unroll
            for (int nb = 0; nb < 4; nb++) {
                uint32_t B0, B1, B2, B3;
                LDSM_X4T(B0, B1, B2, B3, p_base + ks * 16 * 144 + nb * 32);
                mma_bf16(acc[2 * nb], A0, A1, A2, A3, B0, B1);
                mma_bf16(acc[2 * nb + 1], A0, A1, A2, A3, B2, B3);
            }
        }
        __syncthreads();      // all consumers done with buf
        if (tid == 0 && jx + 2 < 32)
            k3_issue(S, ibase, jt0 + jx + 2, buf, buf ? mb1 : mb0);
    }

    // partial writeout
    float* po = g_pout[split];
#pragma unroll
    for (int nt = 0; nt < 8; nt++) {
        const int f0 = nt * 8 + t * 2;
        const int n0 = ibase + mh + g;
        const int n1 = n0 + 8;
#pragma unroll
        for (int q = 0; q < 4; q++) {
            const int n = (q >= 2) ? n1 : n0;
            const int f = f0 + (q & 1);
            po[n * (HH * F_OUT) + h * F_OUT + f] = acc[nt][q];
        }
    }
}

// ---------------- k4: combine splits + skip + ELU --------------------------
__global__ void k4_combine(float* __restrict__ out) {
    const int i4 = (blockIdx.x * 256 + threadIdx.x) * 4;
    const float4 p0 = *(const float4*)&g_pout[0][i4];
    const float4 p1 = *(const float4*)&g_pout[1][i4];
    const float4 sk = *(const float4*)&g_skip[i4];
    float4 o;
    float v;
    v = p0.x + p1.x + sk.x; o.x = (v > 0.f) ? v : (__expf(v) - 1.f);
    v = p0.y + p1.y + sk.y; o.y = (v > 0.f) ? v : (__expf(v) - 1.f);
    v = p0.z + p1.z + sk.z; o.z = (v > 0.f) ? v : (__expf(v) - 1.f);
    v = p0.w + p1.w + sk.w; o.w = (v > 0.f) ? v : (__expf(v) - 1.f);
    *(float4*)&out[i4] = o;
}

// ---------------- launch ---------------------------------------------------
extern "C" void kernel_launch(void* const* d_in, const int* in_sizes, int n_in,
                              void* d_out, int out_size) {
    const float* nodes = (const float*)d_in[0];
    const float* deg   = (const float*)d_in[1];
    const float* bond  = (const float*)d_in[3];
    const float* pp    = (const float*)d_in[4];
    const float* wsrc  = (const float*)d_in[5];
    const float* wtgt  = (const float*)d_in[6];
    const float* skw   = (const float*)d_in[7];
    const int*   cut   = (const int*)d_in[8];

    float* out    = (float*)d_out;
    float* ln_out = (float*)d_out + (size_t)NN * HH * F_OUT;

    const int k3_smem = (int)sizeof(K3Smem);
    cudaFuncSetAttribute(k3_mma, cudaFuncAttributeMaxDynamicSharedMemorySize, k3_smem);

    k0_fused<<<256, 256>>>(nodes, pp, skw, wsrc, wtgt);
    k1_mask_ln<<<NN, 512>>>(deg, bond, cut, ln_out);
    k2_colsum<<<dim3(16, 32), 256>>>();
    k2b_reduce<<<64, 256>>>();
    k3_mma<<<dim3(128, 2), 256, k3_smem>>>();
    k4_combine<<<1024, 256>>>(out);
}